// round 16
// baseline (speedup 1.0000x reference)
#include <cuda_runtime.h>

// Fixed problem shapes (SpanRepresentation_32487132627590)
#define BATCH   4
#define SLEN    2048
#define DIM     768
#define DIM4    (DIM / 4)               // 192
#define NSPAN   4096
#define NROWS   (BATCH * NSPAN)         // 16384
#define CHUNK   32
#define NCHUNK  (SLEN / CHUNK)          // 64
#define NCBLK   (BATCH * NCHUNK)        // 256  -> 2 blocks/SM, occ ~73%
#define PTILE   16                      // prefix tile (no reg spills)
#define OUTW    2364
#define OFF_MEAN 0
#define OFF_XS0  768
#define OFF_P0   1536
#define OFF_XS1  1556
#define OFF_P1   2324
#define OFF_W    2344

// exclusive prefix sums cs[b, s, d], s in [0, SLEN]  (~25.2 MB)
__device__ float g_cs[(size_t)BATCH * (SLEN + 1) * DIM];
// per-chunk sums and their exclusive prefixes
__device__ float g_chunk[(size_t)BATCH * NCHUNK * DIM];
__device__ float g_pref [(size_t)BATCH * NCHUNK * DIM];

// ---------------------------------------------------------------------------
// K1: per-chunk partial sums.  grid = 256, block = 768 (2 blocks/SM).
// ---------------------------------------------------------------------------
__global__ __launch_bounds__(DIM)
void chunksum_kernel(const float* __restrict__ x) {
    const int d  = threadIdx.x;
    const int bc = blockIdx.x;
    const float* p = x + (size_t)bc * CHUNK * DIM + d;

    float a0 = 0.f, a1 = 0.f, a2 = 0.f, a3 = 0.f;
    float a4 = 0.f, a5 = 0.f, a6 = 0.f, a7 = 0.f;
    #pragma unroll
    for (int i = 0; i < CHUNK; i += 8) {
        a0 += p[(size_t)(i + 0) * DIM];
        a1 += p[(size_t)(i + 1) * DIM];
        a2 += p[(size_t)(i + 2) * DIM];
        a3 += p[(size_t)(i + 3) * DIM];
        a4 += p[(size_t)(i + 4) * DIM];
        a5 += p[(size_t)(i + 5) * DIM];
        a6 += p[(size_t)(i + 6) * DIM];
        a7 += p[(size_t)(i + 7) * DIM];
    }
    g_chunk[(size_t)bc * DIM + d] = ((a0 + a1) + (a2 + a3)) + ((a4 + a5) + (a6 + a7));
}

// ---------------------------------------------------------------------------
// K2: exclusive scan of 64 chunk sums per (b,d), tiled 4x16 (no spills).
// grid = 4, block = 768.  L2-hot.
// ---------------------------------------------------------------------------
__global__ __launch_bounds__(DIM)
void chunk_prefix_kernel() {
    const int d = threadIdx.x;
    const int b = blockIdx.x;
    const float* ch = g_chunk + (size_t)b * NCHUNK * DIM + d;
    float*       pf = g_pref  + (size_t)b * NCHUNK * DIM + d;

    float run = 0.f;
    #pragma unroll
    for (int tile = 0; tile < NCHUNK / PTILE; tile++) {
        float v[PTILE];
        #pragma unroll
        for (int k = 0; k < PTILE; k++)
            v[k] = ch[(size_t)(tile * PTILE + k) * DIM];   // 16 independent loads
        #pragma unroll
        for (int k = 0; k < PTILE; k++) {
            pf[(size_t)(tile * PTILE + k) * DIM] = run;
            run += v[k];
        }
    }
}

// ---------------------------------------------------------------------------
// K3: pure streaming scan -> cs.  grid = 256, block = 768 (2 blocks/SM).
// ---------------------------------------------------------------------------
__global__ __launch_bounds__(DIM)
void scan_write_kernel(const float* __restrict__ x) {
    const int d  = threadIdx.x;
    const int bc = blockIdx.x;
    const int b  = bc / NCHUNK;
    const int c  = bc % NCHUNK;

    float run = g_pref[(size_t)bc * DIM + d];   // exclusive chunk prefix

    const float* p = x    + ((size_t)b * SLEN       + (size_t)c * CHUNK) * DIM + d;
    float*       q = g_cs + ((size_t)b * (SLEN + 1) + (size_t)c * CHUNK) * DIM + d;

    #pragma unroll 4
    for (int i = 0; i < CHUNK; i++) {
        q[(size_t)i * DIM] = run;
        run += p[(size_t)i * DIM];
    }
    if (c == NCHUNK - 1) q[(size_t)CHUNK * DIM] = run;   // cs[SLEN]
}

// ---------------------------------------------------------------------------
// K4 (proven, untouched): one block per output row.  grid = 16384, block=192
// ---------------------------------------------------------------------------
__global__ __launch_bounds__(DIM4)
void span_kernel(const float* __restrict__ x,
                 const int* __restrict__ spans,
                 const int* __restrict__ pt_labels,
                 const float* __restrict__ wtab,
                 const float* __restrict__ ptab,
                 float* __restrict__ out) {
    const int bn = blockIdx.x;
    const int b  = bn >> 12;
    const int n  = bn & (NSPAN - 1);
    const int t  = threadIdx.x;

    const int i0 = spans[2 * n + 0];
    const int i1 = spans[2 * n + 1];
    const int width = i1 - i0 + 1;

    const int bins[16] = {0,1,2,3,4,5,7,8,9,10,15,16,31,32,63,64};
    int em = 0;
    #pragma unroll
    for (int i = 1; i < 16; i++) em = (width >= bins[i]) ? i : em;

    const int l0 = pt_labels[i0];
    const int l1 = pt_labels[i1];
    const float inv_w = 1.0f / (float)width;

    const float4 a  = ((const float4*)(g_cs + ((size_t)b * (SLEN + 1) + i0    ) * DIM))[t];
    const float4 bb = ((const float4*)(g_cs + ((size_t)b * (SLEN + 1) + i1 + 1) * DIM))[t];
    const float4 v0 = ((const float4*)(x    + ((size_t)b * SLEN + i0) * DIM))[t];
    const float4 v1 = ((const float4*)(x    + ((size_t)b * SLEN + i1) * DIM))[t];
    float* orow = out + (size_t)bn * OUTW;

    float4 m;
    m.x = (bb.x - a.x) * inv_w;
    m.y = (bb.y - a.y) * inv_w;
    m.z = (bb.z - a.z) * inv_w;
    m.w = (bb.w - a.w) * inv_w;

    ((float4*)(orow + OFF_MEAN))[t] = m;
    ((float4*)(orow + OFF_XS0 ))[t] = v0;
    ((float4*)(orow + OFF_XS1 ))[t] = v1;

    if (t < 5) {
        ((float4*)(orow + OFF_P0))[t] = ((const float4*)(ptab + l0 * 20))[t];
        ((float4*)(orow + OFF_P1))[t] = ((const float4*)(ptab + l1 * 20))[t];
        ((float4*)(orow + OFF_W ))[t] = ((const float4*)(wtab + em * 20))[t];
    }
}

// ---------------------------------------------------------------------------
extern "C" void kernel_launch(void* const* d_in, const int* in_sizes, int n_in,
                              void* d_out, int out_size) {
    const float* x      = (const float*)d_in[0];
    const int*   spans  = (const int*)d_in[1];
    const int*   labels = (const int*)d_in[2];
    const float* wtab   = (const float*)d_in[3];
    const float* ptab   = (const float*)d_in[4];
    float*       out    = (float*)d_out;

    chunksum_kernel    <<<NCBLK, DIM>>>(x);
    chunk_prefix_kernel<<<BATCH, DIM>>>();
    scan_write_kernel  <<<NCBLK, DIM>>>(x);
    span_kernel        <<<NROWS, DIM4>>>(x, spans, labels, wtab, ptab, out);
}

// round 17
// speedup vs baseline: 1.1011x; 1.1011x over previous
#include <cuda_runtime.h>

// Fixed problem shapes (SpanRepresentation_32487132627590)
#define BATCH   4
#define SLEN    2048
#define DIM     768
#define DIM4    (DIM / 4)               // 192
#define NSPAN   4096
#define NROWS   (BATCH * NSPAN)         // 16384
#define CHUNK   64
#define NCHUNK  (SLEN / CHUNK)          // 32
#define NCBLK   (BATCH * NCHUNK)        // 128
#define F4_PER_CHUNK (CHUNK * DIM4)     // 12288 float4 per chunk
#define OUTW    2364
#define OFF_MEAN 0
#define OFF_XS0  768
#define OFF_P0   1536
#define OFF_XS1  1556
#define OFF_P1   2324
#define OFF_W    2344

// exclusive prefix sums cs[b, s, d], s in [0, SLEN]  (~25.2 MB)
__device__ float g_cs[(size_t)BATCH * (SLEN + 1) * DIM];
// per-chunk sums
__device__ float g_chunk[(size_t)BATCH * NCHUNK * DIM];

static __device__ __forceinline__ float4 f4add(float4 a, float4 b) {
    a.x += b.x; a.y += b.y; a.z += b.z; a.w += b.w; return a;
}

// ---------------------------------------------------------------------------
// K1: per-chunk partial sums, CONTIGUOUS float4 stream + smem fold.
// grid = 128, block = 768.  Thread t owns column-group (t%192) and
// row-residue (t/192); 16 flat iterations of LDG.128, 4 accumulators.
// In-flight ~48 KB/SM (4x every previous attempt).
// ---------------------------------------------------------------------------
__global__ __launch_bounds__(DIM)
void chunksum_kernel(const float* __restrict__ x) {
    const int t  = threadIdx.x;              // 0..767
    const int bc = blockIdx.x;               // chunk id
    const float4* p = (const float4*)(x + (size_t)bc * CHUNK * DIM);

    // 16 fully contiguous block-wide sweeps: iter j covers rows [4j, 4j+4)
    float4 a0 = p[0*DIM + t];                // DIM float4 per 4-row sweep group? no:
    // stride per iteration is 768 float4 = 4 rows
    float4 a1 = p[1*768 + t];
    float4 a2 = p[2*768 + t];
    float4 a3 = p[3*768 + t];
    #pragma unroll
    for (int j = 4; j < 16; j += 4) {
        a0 = f4add(a0, p[(j+0)*768 + t]);
        a1 = f4add(a1, p[(j+1)*768 + t]);
        a2 = f4add(a2, p[(j+2)*768 + t]);
        a3 = f4add(a3, p[(j+3)*768 + t]);
    }
    float4 s = f4add(f4add(a0, a1), f4add(a2, a3));  // sum of this thread's 16 rows

    // fold the 4 row-residues (threads t, t+192, t+384, t+576 share a column)
    __shared__ float4 sm[DIM];
    sm[t] = s;
    __syncthreads();
    if (t < DIM4) {
        float4 tot = f4add(f4add(sm[t], sm[t + 192]),
                           f4add(sm[t + 384], sm[t + 576]));
        ((float4*)(g_chunk + (size_t)bc * DIM))[t] = tot;
    }
}

// ---------------------------------------------------------------------------
// K2 (R11/R15-proven): scan -> cs with inline chunk-prefix (unrolled,
// predicated, 32 independent L2-hot loads).  grid = 128, block = 768
// ---------------------------------------------------------------------------
__global__ __launch_bounds__(DIM)
void scan_write_kernel(const float* __restrict__ x) {
    const int d  = threadIdx.x;
    const int bc = blockIdx.x;
    const int b  = bc / NCHUNK;
    const int c  = bc % NCHUNK;

    const float* ch = g_chunk + (size_t)b * NCHUNK * DIM + d;
    float run = 0.f;
    #pragma unroll
    for (int cc = 0; cc < NCHUNK; cc++) {
        float v = (cc < c) ? ch[(size_t)cc * DIM] : 0.f;
        run += v;
    }

    const float* p = x    + ((size_t)b * SLEN       + (size_t)c * CHUNK) * DIM + d;
    float*       q = g_cs + ((size_t)b * (SLEN + 1) + (size_t)c * CHUNK) * DIM + d;

    #pragma unroll 4
    for (int i = 0; i < CHUNK; i++) {
        q[(size_t)i * DIM] = run;
        run += p[(size_t)i * DIM];
    }
    if (c == NCHUNK - 1) q[(size_t)CHUNK * DIM] = run;   // cs[SLEN]
}

// ---------------------------------------------------------------------------
// K3 (proven, untouched): one block per output row.  grid = 16384, block=192
// ---------------------------------------------------------------------------
__global__ __launch_bounds__(DIM4)
void span_kernel(const float* __restrict__ x,
                 const int* __restrict__ spans,
                 const int* __restrict__ pt_labels,
                 const float* __restrict__ wtab,
                 const float* __restrict__ ptab,
                 float* __restrict__ out) {
    const int bn = blockIdx.x;
    const int b  = bn >> 12;
    const int n  = bn & (NSPAN - 1);
    const int t  = threadIdx.x;

    const int i0 = spans[2 * n + 0];
    const int i1 = spans[2 * n + 1];
    const int width = i1 - i0 + 1;

    const int bins[16] = {0,1,2,3,4,5,7,8,9,10,15,16,31,32,63,64};
    int em = 0;
    #pragma unroll
    for (int i = 1; i < 16; i++) em = (width >= bins[i]) ? i : em;

    const int l0 = pt_labels[i0];
    const int l1 = pt_labels[i1];
    const float inv_w = 1.0f / (float)width;

    const float4 a  = ((const float4*)(g_cs + ((size_t)b * (SLEN + 1) + i0    ) * DIM))[t];
    const float4 bb = ((const float4*)(g_cs + ((size_t)b * (SLEN + 1) + i1 + 1) * DIM))[t];
    const float4 v0 = ((const float4*)(x    + ((size_t)b * SLEN + i0) * DIM))[t];
    const float4 v1 = ((const float4*)(x    + ((size_t)b * SLEN + i1) * DIM))[t];
    float* orow = out + (size_t)bn * OUTW;

    float4 m;
    m.x = (bb.x - a.x) * inv_w;
    m.y = (bb.y - a.y) * inv_w;
    m.z = (bb.z - a.z) * inv_w;
    m.w = (bb.w - a.w) * inv_w;

    ((float4*)(orow + OFF_MEAN))[t] = m;
    ((float4*)(orow + OFF_XS0 ))[t] = v0;
    ((float4*)(orow + OFF_XS1 ))[t] = v1;

    if (t < 5) {
        ((float4*)(orow + OFF_P0))[t] = ((const float4*)(ptab + l0 * 20))[t];
        ((float4*)(orow + OFF_P1))[t] = ((const float4*)(ptab + l1 * 20))[t];
        ((float4*)(orow + OFF_W ))[t] = ((const float4*)(wtab + em * 20))[t];
    }
}

// ---------------------------------------------------------------------------
extern "C" void kernel_launch(void* const* d_in, const int* in_sizes, int n_in,
                              void* d_out, int out_size) {
    const float* x      = (const float*)d_in[0];
    const int*   spans  = (const int*)d_in[1];
    const int*   labels = (const int*)d_in[2];
    const float* wtab   = (const float*)d_in[3];
    const float* ptab   = (const float*)d_in[4];
    float*       out    = (float*)d_out;

    chunksum_kernel  <<<NCBLK, DIM>>>(x);
    scan_write_kernel<<<NCBLK, DIM>>>(x);
    span_kernel      <<<NROWS, DIM4>>>(x, spans, labels, wtab, ptab, out);
}